// round 15
// baseline (speedup 1.0000x reference)
#include <cuda_runtime.h>
#include <math.h>

// Problem-fixed maxima (shapes are fixed by the dataset): N=100000, E=1600000
#define NMAX 100000
#define EMAX 1600000

// Scratch (static device globals — no runtime allocation allowed)
__device__ float g_P1[(size_t)NMAX * 128];   // atom_fea @ W1^T   (51.2 MB)
__device__ float g_P2[(size_t)NMAX * 128];   // atom_fea @ W2^T   (51.2 MB)
__device__ float g_Z [(size_t)EMAX * 128];   // pre-BN fc output  (819 MB)
__device__ float g_s1[128], g_q1[128], g_scale1[128], g_shift1[128];
__device__ float g_s2[64],  g_q2[64],  g_scale2[64],  g_shift2[64];
__device__ int   g_idx64;

// ---------------------------------------------------------------------------
// k_init: zero the stat accumulators (graph is replayed!) and detect whether
// src/dst arrived as int64 (high words all zero) or int32.
// ---------------------------------------------------------------------------
__global__ void k_init(const unsigned* __restrict__ src, int E)
{
    int t = threadIdx.x;
    __shared__ int bad;
    if (t == 0) bad = 0;
    if (t < 128) { g_s1[t] = 0.f; g_q1[t] = 0.f; }
    if (t < 64)  { g_s2[t] = 0.f; g_q2[t] = 0.f; }
    __syncthreads();
    int S = min(256, E >> 1);
    if (t < S) {
        // If data is int64 little-endian with values < 2^31, every odd 32-bit
        // word is 0. If it is int32, odd words are random indices (P(all 0)~0).
        if (src[2 * t + 1] != 0u) atomicExch(&bad, 1);
    }
    __syncthreads();
    if (t == 0) g_idx64 = bad ? 0 : 1;
}

// ---------------------------------------------------------------------------
// k_P: P1[n,j] = sum_{k<64} atom[n,k]*fcw[j,k]
//      P2[n,j] = sum_{k<64} atom[n,k]*fcw[j,64+k]
// One combined GEMM: P(N x 256) = A(N x 64) @ Wp(64 x 256).
// Tile: 64 atoms x 256 outputs per block, 256 threads, 8x8 micro-tiles.
// smem: sW[k][j] stride 260 (66560 B), sA[k][a] stride 68 (17408 B).
// ---------------------------------------------------------------------------
__global__ __launch_bounds__(256, 2) void k_P(
    const float* __restrict__ atom, const float* __restrict__ fcw, int N)
{
    extern __shared__ float sm[];
    float* sW = sm;              // [64][260]
    float* sA = sW + 64 * 260;   // [64][68]

    int tid  = threadIdx.x;
    int tcol = tid & 31;         // 32 groups of 8 output cols  -> 256
    int trow = tid >> 5;         //  8 groups of 8 atoms        -> 64
    int n0   = blockIdx.x * 64;

    // Load Wp transposed into sW[k][j]
    for (int u = tid; u < 256 * 16; u += 256) {
        int j = u >> 4, k4 = u & 15;
        const float* b = (j < 128) ? (fcw + (size_t)j * 256 + k4 * 4)
                                   : (fcw + (size_t)(j - 128) * 256 + 64 + k4 * 4);
        float4 w = *(const float4*)b;
        sW[(k4 * 4 + 0) * 260 + j] = w.x;
        sW[(k4 * 4 + 1) * 260 + j] = w.y;
        sW[(k4 * 4 + 2) * 260 + j] = w.z;
        sW[(k4 * 4 + 3) * 260 + j] = w.w;
    }
    // Load atom tile transposed into sA[k][a]
    for (int u = tid; u < 64 * 16; u += 256) {
        int a = u >> 4, k4 = u & 15;
        int n = n0 + a;
        float4 v = make_float4(0.f, 0.f, 0.f, 0.f);
        if (n < N) v = *(const float4*)(atom + (size_t)n * 64 + k4 * 4);
        sA[(k4 * 4 + 0) * 68 + a] = v.x;
        sA[(k4 * 4 + 1) * 68 + a] = v.y;
        sA[(k4 * 4 + 2) * 68 + a] = v.z;
        sA[(k4 * 4 + 3) * 68 + a] = v.w;
    }
    __syncthreads();

    float acc[8][8];
#pragma unroll
    for (int i = 0; i < 8; i++)
#pragma unroll
        for (int c = 0; c < 8; c++) acc[i][c] = 0.f;

#pragma unroll 4
    for (int k = 0; k < 64; k++) {
        const float* ap = sA + k * 68  + trow * 8;
        const float* wp = sW + k * 260 + tcol * 8;
        float4 A0 = *(const float4*)ap, A1 = *(const float4*)(ap + 4);
        float4 W0 = *(const float4*)wp, W1 = *(const float4*)(wp + 4);
        float a[8] = {A0.x, A0.y, A0.z, A0.w, A1.x, A1.y, A1.z, A1.w};
        float w[8] = {W0.x, W0.y, W0.z, W0.w, W1.x, W1.y, W1.z, W1.w};
#pragma unroll
        for (int i = 0; i < 8; i++)
#pragma unroll
            for (int c = 0; c < 8; c++)
                acc[i][c] = fmaf(a[i], w[c], acc[i][c]);
    }

    int j0 = tcol * 8;
#pragma unroll
    for (int i = 0; i < 8; i++) {
        int n = n0 + trow * 8 + i;
        if (n >= N) continue;
        float4 v0 = make_float4(acc[i][0], acc[i][1], acc[i][2], acc[i][3]);
        float4 v1 = make_float4(acc[i][4], acc[i][5], acc[i][6], acc[i][7]);
        float* dst = (j0 < 128) ? (g_P1 + (size_t)n * 128 + j0)
                                : (g_P2 + (size_t)n * 128 + (j0 - 128));
        *(float4*)dst       = v0;
        *(float4*)(dst + 4) = v1;
    }
}

// ---------------------------------------------------------------------------
// k_edge1: z[e,:] = Eg[e,:] @ W3^T + fc_b + P1[dst[e],:] + P2[src[e],:]
// Stores z (fp32) and accumulates per-column sum / sumsq for BN1.
// Tile: 128 edges x 128 outputs, K=128 in two 64-chunks. 256 threads, 8x8.
// smem: sW[k=0..127][j] stride 132 (67584 B) + sA[k][e] stride 132 (33792 B)
//       + stats (1 KB) + indices (1 KB)  => 103424 B dynamic.
// ---------------------------------------------------------------------------
#define KC 64
__global__ __launch_bounds__(256, 2) void k_edge1(
    const float* __restrict__ eg, const float* __restrict__ fcw,
    const float* __restrict__ fcb,
    const void* __restrict__ srcp, const void* __restrict__ dstp, int E)
{
    extern __shared__ float sm[];
    float* sW    = sm;               // [128][132]
    float* sA    = sW + 128 * 132;   // [64][132]
    float* s_sum = sA + 64 * 132;    // [128]
    float* s_sq  = s_sum + 128;      // [128]
    int*   s_dst = (int*)(s_sq + 128);   // [128]
    int*   s_src = s_dst + 128;          // [128]

    int tid  = threadIdx.x;
    int tcol = tid & 15;             // 16 groups of 8 cols  -> 128
    int trow = tid >> 4;             // 16 groups of 8 edges -> 128
    int e0   = blockIdx.x * 128;
    int is64 = g_idx64;

    if (tid < 128) {
        s_sum[tid] = 0.f; s_sq[tid] = 0.f;
        int e = e0 + tid, d = 0, s = 0;
        if (e < E) {
            if (is64) { d = (int)((const long long*)dstp)[e]; s = (int)((const long long*)srcp)[e]; }
            else      { d = ((const int*)dstp)[e];            s = ((const int*)srcp)[e]; }
        }
        s_dst[tid] = d; s_src[tid] = s;
    }

    // W3^T into sW[k][j]: sW[k][j] = fcw[j*256 + 128 + k]
    for (int u = tid; u < 128 * 32; u += 256) {
        int j = u >> 5, k4 = u & 31;
        float4 w = *(const float4*)(fcw + (size_t)j * 256 + 128 + k4 * 4);
        sW[(k4 * 4 + 0) * 132 + j] = w.x;
        sW[(k4 * 4 + 1) * 132 + j] = w.y;
        sW[(k4 * 4 + 2) * 132 + j] = w.z;
        sW[(k4 * 4 + 3) * 132 + j] = w.w;
    }

    float acc[8][8];
#pragma unroll
    for (int i = 0; i < 8; i++)
#pragma unroll
        for (int c = 0; c < 8; c++) acc[i][c] = 0.f;

    for (int kc = 0; kc < 128; kc += KC) {
        __syncthreads();
        // Load edge chunk transposed: sA[k][e], 128 edges x 64 k
        for (int u = tid; u < 128 * (KC / 4); u += 256) {
            int eL = u >> 4, k4 = u & 15;
            int e = e0 + eL;
            float4 v = make_float4(0.f, 0.f, 0.f, 0.f);
            if (e < E) v = *(const float4*)(eg + (size_t)e * 128 + kc + k4 * 4);
            sA[(k4 * 4 + 0) * 132 + eL] = v.x;
            sA[(k4 * 4 + 1) * 132 + eL] = v.y;
            sA[(k4 * 4 + 2) * 132 + eL] = v.z;
            sA[(k4 * 4 + 3) * 132 + eL] = v.w;
        }
        __syncthreads();
#pragma unroll 4
        for (int k = 0; k < KC; k++) {
            const float* ap = sA + k * 132 + trow * 8;
            const float* wp = sW + (kc + k) * 132 + tcol * 8;
            float4 A0 = *(const float4*)ap, A1 = *(const float4*)(ap + 4);
            float4 W0 = *(const float4*)wp, W1 = *(const float4*)(wp + 4);
            float a[8] = {A0.x, A0.y, A0.z, A0.w, A1.x, A1.y, A1.z, A1.w};
            float w[8] = {W0.x, W0.y, W0.z, W0.w, W1.x, W1.y, W1.z, W1.w};
#pragma unroll
            for (int i = 0; i < 8; i++)
#pragma unroll
                for (int c = 0; c < 8; c++)
                    acc[i][c] = fmaf(a[i], w[c], acc[i][c]);
        }
    }

    // Epilogue: add bias + gathered atom projections, store z, reduce stats
    int j0 = tcol * 8;
    float4 B0 = *(const float4*)(fcb + j0);
    float4 B1 = *(const float4*)(fcb + j0 + 4);
    float bia[8] = {B0.x, B0.y, B0.z, B0.w, B1.x, B1.y, B1.z, B1.w};

    float csum[8], csq[8];
#pragma unroll
    for (int c = 0; c < 8; c++) { csum[c] = 0.f; csq[c] = 0.f; }

#pragma unroll
    for (int i = 0; i < 8; i++) {
        int eL = trow * 8 + i, e = e0 + eL;
        if (e >= E) continue;
        int d = s_dst[eL], s = s_src[eL];
        const float* p1 = g_P1 + (size_t)d * 128 + j0;
        const float* p2 = g_P2 + (size_t)s * 128 + j0;
        float4 x0 = *(const float4*)p1, x1 = *(const float4*)(p1 + 4);
        float4 y0 = *(const float4*)p2, y1 = *(const float4*)(p2 + 4);
        float z[8];
        z[0] = acc[i][0] + bia[0] + x0.x + y0.x;
        z[1] = acc[i][1] + bia[1] + x0.y + y0.y;
        z[2] = acc[i][2] + bia[2] + x0.z + y0.z;
        z[3] = acc[i][3] + bia[3] + x0.w + y0.w;
        z[4] = acc[i][4] + bia[4] + x1.x + y1.x;
        z[5] = acc[i][5] + bia[5] + x1.y + y1.y;
        z[6] = acc[i][6] + bia[6] + x1.z + y1.z;
        z[7] = acc[i][7] + bia[7] + x1.w + y1.w;
        float* zo = g_Z + (size_t)e * 128 + j0;
        *(float4*)zo       = make_float4(z[0], z[1], z[2], z[3]);
        *(float4*)(zo + 4) = make_float4(z[4], z[5], z[6], z[7]);
#pragma unroll
        for (int c = 0; c < 8; c++) {
            csum[c] += z[c];
            csq[c]  = fmaf(z[c], z[c], csq[c]);
        }
    }
#pragma unroll
    for (int c = 0; c < 8; c++) {
        atomicAdd(&s_sum[j0 + c], csum[c]);
        atomicAdd(&s_sq [j0 + c], csq[c]);
    }
    __syncthreads();
    if (tid < 128) {
        atomicAdd(&g_s1[tid], s_sum[tid]);
        atomicAdd(&g_q1[tid], s_sq[tid]);
    }
}

// ---------------------------------------------------------------------------
// Fold BN1 into affine scale/shift per column
// ---------------------------------------------------------------------------
__global__ void k_bn1fin(const float* __restrict__ w, const float* __restrict__ b,
                         float invE)
{
    int j = threadIdx.x;  // 128
    float m  = g_s1[j] * invE;
    float v  = g_q1[j] * invE - m * m;
    float sc = w[j] * rsqrtf(v + 1e-5f);
    g_scale1[j] = sc;
    g_shift1[j] = fmaf(-m, sc, b[j]);
}

// ---------------------------------------------------------------------------
// k_edge2: messages = sigmoid(gate)*softplus(core) on BN1-normalized z;
// scatter-add into d_out (aggr). 16 threads per edge, 4 columns each.
// ---------------------------------------------------------------------------
__global__ void k_edge2(const void* __restrict__ dstp, int E, float* __restrict__ out)
{
    int t = blockIdx.x * blockDim.x + threadIdx.x;
    int e = t >> 4;
    if (e >= E) return;
    int j = (t & 15) * 4;
    int d = g_idx64 ? (int)((const long long*)dstp)[e] : ((const int*)dstp)[e];

    const float* zr = g_Z + (size_t)e * 128;
    float4 gz = *(const float4*)(zr + j);
    float4 cz = *(const float4*)(zr + 64 + j);
    float gv[4] = {gz.x, gz.y, gz.z, gz.w};
    float cv[4] = {cz.x, cz.y, cz.z, cz.w};
    float m[4];
#pragma unroll
    for (int c = 0; c < 4; c++) {
        float gg  = fmaf(gv[c], g_scale1[j + c],      g_shift1[j + c]);
        float cc  = fmaf(cv[c], g_scale1[64 + j + c], g_shift1[64 + j + c]);
        float sig = 1.f / (1.f + __expf(-gg));
        float sp  = fmaxf(cc, 0.f) + log1pf(__expf(-fabsf(cc)));
        m[c] = sig * sp;
    }
    float* o = out + (size_t)d * 64 + j;
    atomicAdd(o + 0, m[0]);
    atomicAdd(o + 1, m[1]);
    atomicAdd(o + 2, m[2]);
    atomicAdd(o + 3, m[3]);
}

// ---------------------------------------------------------------------------
// BN2 stats over aggr (d_out). Grid-stride; stride is a multiple of 64 so each
// thread stays on one column.
// ---------------------------------------------------------------------------
__global__ void k_stats2(const float* __restrict__ out, int total)
{
    __shared__ float ss[64], sq[64];
    int tid = threadIdx.x;
    if (tid < 64) { ss[tid] = 0.f; sq[tid] = 0.f; }
    __syncthreads();
    int i0 = blockIdx.x * blockDim.x + tid;
    int stride = gridDim.x * blockDim.x;
    float s = 0.f, q = 0.f;
    for (int i = i0; i < total; i += stride) {
        float v = out[i];
        s += v;
        q = fmaf(v, v, q);
    }
    int col = i0 & 63;
    atomicAdd(&ss[col], s);
    atomicAdd(&sq[col], q);
    __syncthreads();
    if (tid < 64) {
        atomicAdd(&g_s2[tid], ss[tid]);
        atomicAdd(&g_q2[tid], sq[tid]);
    }
}

__global__ void k_bn2fin(const float* __restrict__ w, const float* __restrict__ b,
                         float invN)
{
    int j = threadIdx.x;  // 64
    float m  = g_s2[j] * invN;
    float v  = g_q2[j] * invN - m * m;
    float sc = w[j] * rsqrtf(v + 1e-5f);
    g_scale2[j] = sc;
    g_shift2[j] = fmaf(-m, sc, b[j]);
}

// ---------------------------------------------------------------------------
// Final: out = softplus(atom_fea + BN2(aggr)), in place on d_out.
// ---------------------------------------------------------------------------
__global__ void k_final(const float* __restrict__ atom, float* __restrict__ out,
                        int total)
{
    int i = blockIdx.x * blockDim.x + threadIdx.x;
    if (i >= total) return;
    int j = i & 63;
    float v = atom[i] + fmaf(out[i], g_scale2[j], g_shift2[j]);
    out[i] = fmaxf(v, 0.f) + log1pf(__expf(-fabsf(v)));
}

// ---------------------------------------------------------------------------
extern "C" void kernel_launch(void* const* d_in, const int* in_sizes, int n_in,
                              void* d_out, int out_size)
{
    const float* atom = (const float*)d_in[0];
    const float* edge = (const float*)d_in[1];
    const float* fcw  = (const float*)d_in[2];
    const float* fcb  = (const float*)d_in[3];
    const float* bn1w = (const float*)d_in[4];
    const float* bn1b = (const float*)d_in[5];
    const float* bn2w = (const float*)d_in[6];
    const float* bn2b = (const float*)d_in[7];
    const void*  src  = d_in[8];
    const void*  dst  = d_in[9];

    int N = in_sizes[0] / 64;    // atom_fea is (N, 64)
    int E = in_sizes[1] / 128;   // edge_fea is (E, 128)

    // Opt-in to >48KB dynamic smem (idempotent; not a stream op, capture-safe)
    cudaFuncSetAttribute(k_P,     cudaFuncAttributeMaxDynamicSharedMemorySize, 83968);
    cudaFuncSetAttribute(k_edge1, cudaFuncAttributeMaxDynamicSharedMemorySize, 103424);

    k_init<<<1, 256>>>((const unsigned*)src, E);
    cudaMemsetAsync(d_out, 0, (size_t)N * 64 * sizeof(float));

    k_P<<<(N + 63) / 64, 256, 83968>>>(atom, fcw, N);
    k_edge1<<<(E + 127) / 128, 256, 103424>>>(edge, fcw, fcb, src, dst, E);
    k_bn1fin<<<1, 128>>>(bn1w, bn1b, 1.f / (float)E);

    long long T2 = (long long)E * 16;
    k_edge2<<<(int)((T2 + 255) / 256), 256>>>(dst, E, (float*)d_out);

    k_stats2<<<512, 256>>>((const float*)d_out, N * 64);
    k_bn2fin<<<1, 64>>>(bn2w, bn2b, 1.f / (float)N);
    k_final<<<(N * 64 + 255) / 256, 256>>>(atom, (float*)d_out, N * 64);
}